// round 2
// baseline (speedup 1.0000x reference)
#include <cuda_runtime.h>

#define T 8192
#define D 128
#define C 16
#define NM 4

// Scratch (device globals — no allocation allowed)
__device__ float g_sq[T];
__device__ float g_Y[T * C];
__device__ int   g_nbr[T * 2];

// ---------------------------------------------------------------------------
// sq[i] = sum_d X[i,d]^2   (warp per row)
// ---------------------------------------------------------------------------
__global__ void sq_kernel(const float* __restrict__ X) {
    int row  = blockIdx.x * 8 + (threadIdx.x >> 5);
    int lane = threadIdx.x & 31;
    const float* xr = X + row * D;
    float s = 0.f;
#pragma unroll
    for (int q = 0; q < 4; q++) {
        float v = xr[lane + 32 * q];
        s = fmaf(v, v, s);
    }
#pragma unroll
    for (int o = 16; o; o >>= 1) s += __shfl_xor_sync(0xffffffffu, s, o);
    if (lane == 0) g_sq[row] = s;
}

// ---------------------------------------------------------------------------
// Y = X @ W + b ; also writes the first T rows of the output.
// Block: 256 threads = 16 rows x 16 cols. W cached in smem.
// ---------------------------------------------------------------------------
__global__ void y_kernel(const float* __restrict__ X, const float* __restrict__ W,
                         const float* __restrict__ b, float* __restrict__ out) {
    __shared__ float Ws[D * C];
    int tid = threadIdx.x;
    for (int p = tid; p < D * C; p += 256) Ws[p] = W[p];
    __syncthreads();

    int i = blockIdx.x * 16 + (tid >> 4);
    int c = tid & 15;
    const float* xr = X + i * D;
    float acc = b[c];
#pragma unroll 8
    for (int d = 0; d < D; d++) acc = fmaf(xr[d], Ws[d * C + c], acc);
    g_Y[i * C + c] = acc;
    out[i * C + c] = acc;
}

// ---------------------------------------------------------------------------
// KNN: for each row i find the 2 nearest neighbors (excluding self) by
// v_j = sq_j - 2 * dot(x_i, x_j)  (rank-equivalent to the reference distance).
// Tile: 64 (i) x 128 (j) per block, K streamed in chunks of 16.
// 256 threads, 4x8 micro-tile, fused top-2 epilogue with lower-index tiebreak.
// ---------------------------------------------------------------------------
__global__ __launch_bounds__(256) void knn_kernel(const float* __restrict__ X) {
    __shared__ float As[D][64];    // 32KB, [k][ii] transposed, full K resident
    __shared__ float Bs[16][128];  //  8KB, [k][jj] transposed, one K-chunk
    __shared__ float SqJ[128];

    int tid = threadIdx.x;
    int tx  = tid & 15;   // j dim
    int ty  = tid >> 4;   // i dim
    int ibase = blockIdx.x * 64;

    // Load + transpose A tile once (consecutive tid -> consecutive rows:
    // scalar-scattered LDG but conflict-free STS; only 32KB once per block).
#pragma unroll
    for (int p = 0; p < 8; p++) {
        int idx = tid + p * 256;
        int row = idx & 63;
        int kc  = idx >> 6;  // 0..31 float4 chunks
        float4 v = *(const float4*)(X + (ibase + row) * D + kc * 4);
        As[kc * 4 + 0][row] = v.x;
        As[kc * 4 + 1][row] = v.y;
        As[kc * 4 + 2][row] = v.z;
        As[kc * 4 + 3][row] = v.w;
    }

    float v0[4], v1[4];
    int   j0[4], j1[4];
    int   irow[4];
#pragma unroll
    for (int m = 0; m < 4; m++) {
        v0[m] = v1[m] = 3.4e38f;
        j0[m] = j1[m] = 0x7fffffff;
        irow[m] = ibase + ty * 4 + m;
    }

    for (int jt = 0; jt < T / 128; jt++) {
        int jbase = jt * 128;
        float acc[4][8];
#pragma unroll
        for (int m = 0; m < 4; m++)
#pragma unroll
            for (int n = 0; n < 8; n++) acc[m][n] = 0.f;

        for (int ch = 0; ch < 8; ch++) {
            __syncthreads();  // previous chunk fully consumed
#pragma unroll
            for (int p = 0; p < 2; p++) {
                int idx = tid + p * 256;
                int row = idx & 127;
                int kc  = idx >> 7;  // 0..3
                float4 v = *(const float4*)(X + (jbase + row) * D + ch * 16 + kc * 4);
                Bs[kc * 4 + 0][row] = v.x;
                Bs[kc * 4 + 1][row] = v.y;
                Bs[kc * 4 + 2][row] = v.z;
                Bs[kc * 4 + 3][row] = v.w;
            }
            if (ch == 0 && tid < 128) SqJ[tid] = g_sq[jbase + tid];
            __syncthreads();

#pragma unroll
            for (int kk = 0; kk < 16; kk++) {
                float4 a  = *(const float4*)&As[ch * 16 + kk][ty * 4];
                float4 b0 = *(const float4*)&Bs[kk][tx * 8];
                float4 b1 = *(const float4*)&Bs[kk][tx * 8 + 4];
                float av[4] = {a.x, a.y, a.z, a.w};
                float bv[8] = {b0.x, b0.y, b0.z, b0.w, b1.x, b1.y, b1.z, b1.w};
#pragma unroll
                for (int m = 0; m < 4; m++)
#pragma unroll
                    for (int n = 0; n < 8; n++)
                        acc[m][n] = fmaf(av[m], bv[n], acc[m][n]);
            }
        }

        // top-2 update (exclude self; tie -> lower index, matching top_k)
#pragma unroll
        for (int n = 0; n < 8; n++) {
            int   j  = jbase + tx * 8 + n;
            float sj = SqJ[tx * 8 + n];
#pragma unroll
            for (int m = 0; m < 4; m++) {
                float v = fmaf(-2.f, acc[m][n], sj);
                if (j != irow[m]) {
                    if (v < v0[m] || (v == v0[m] && j < j0[m])) {
                        v1[m] = v0[m]; j1[m] = j0[m];
                        v0[m] = v;     j0[m] = j;
                    } else if (v < v1[m] || (v == v1[m] && j < j1[m])) {
                        v1[m] = v;     j1[m] = j;
                    }
                }
            }
        }
    }

    // Cross-thread merge (16 tx threads per row, 2 candidates each).
    __syncthreads();
    float* candV = (float*)&As[0][0];   // 64*32 floats
    int*   candI = (int*)&As[32][0];    // 64*32 ints
#pragma unroll
    for (int m = 0; m < 4; m++) {
        int row = ty * 4 + m;
        candV[row * 32 + tx * 2]     = v0[m];
        candV[row * 32 + tx * 2 + 1] = v1[m];
        candI[row * 32 + tx * 2]     = j0[m];
        candI[row * 32 + tx * 2 + 1] = j1[m];
    }
    __syncthreads();
    if (tid < 64) {
        float b0v = 3.4e38f, b1v = 3.4e38f;
        int   b0i = 0x7fffffff, b1i = 0x7fffffff;
        for (int q = 0; q < 32; q++) {
            float v  = candV[tid * 32 + q];
            int   jj = candI[tid * 32 + q];
            if (v < b0v || (v == b0v && jj < b0i)) {
                b1v = b0v; b1i = b0i; b0v = v; b0i = jj;
            } else if (v < b1v || (v == b1v && jj < b1i)) {
                b1v = v; b1i = jj;
            }
        }
        g_nbr[(ibase + tid) * 2]     = b0i;
        g_nbr[(ibase + tid) * 2 + 1] = b1i;
    }
}

// ---------------------------------------------------------------------------
// Synthetic rows, computed in logit space (linearity of W):
// out[T+s] = Y[src] + gaps[s] * (Y[chosen] - Y[src])
// ---------------------------------------------------------------------------
__global__ void syn_kernel(const int* __restrict__ nn_idx,
                           const float* __restrict__ gaps,
                           float* __restrict__ out) {
    int idx = blockIdx.x * 256 + threadIdx.x;  // 0 .. NM*T*C-1
    int s   = idx >> 4;
    int c   = idx & 15;
    int src = s >> 2;
    int k   = nn_idx[s] & 1;
    int ch  = g_nbr[src * 2 + k];
    float g  = gaps[s];
    float ys = g_Y[src * C + c];
    float yc = g_Y[ch * C + c];
    out[(T + s) * C + c] = ys + g * (yc - ys);
}

// ---------------------------------------------------------------------------
extern "C" void kernel_launch(void* const* d_in, const int* in_sizes, int n_in,
                              void* d_out, int out_size) {
    const float* X      = (const float*)d_in[0];
    const int*   nn_idx = (const int*)d_in[1];
    const float* gaps   = (const float*)d_in[2];
    const float* W      = (const float*)d_in[3];
    const float* b      = (const float*)d_in[4];
    float* out = (float*)d_out;

    sq_kernel <<<T / 8,  256>>>(X);
    y_kernel  <<<T / 16, 256>>>(X, W, b, out);
    knn_kernel<<<T / 64, 256>>>(X);
    syn_kernel<<<NM * T * C / 256, 256>>>(nn_idx, gaps, out);
}

// round 3
// speedup vs baseline: 1.0202x; 1.0202x over previous
#include <cuda_runtime.h>

#define T 8192
#define D 128
#define C 16
#define NM 4

typedef unsigned long long u64;

// Scratch (device globals — no allocation allowed)
__device__ float g_sq[T];
__device__ float g_Y[T * C];
__device__ int   g_nbr[T * 2];

// Packed dual-fp32 FMA (sm_100+; 2 independent rn FMAs per FMA-pipe slot)
__device__ __forceinline__ u64 fma2(u64 a, u64 b, u64 c) {
    u64 d;
    asm("fma.rn.f32x2 %0, %1, %2, %3;" : "=l"(d) : "l"(a), "l"(b), "l"(c));
    return d;
}
__device__ __forceinline__ void unpack2(float& lo, float& hi, u64 v) {
    asm("mov.b64 {%0, %1}, %2;" : "=f"(lo), "=f"(hi) : "l"(v));
}

// ---------------------------------------------------------------------------
// sq[i] = sum_d X[i,d]^2   (warp per row)
// ---------------------------------------------------------------------------
__global__ void sq_kernel(const float* __restrict__ X) {
    int row  = blockIdx.x * 8 + (threadIdx.x >> 5);
    int lane = threadIdx.x & 31;
    const float* xr = X + row * D;
    float s = 0.f;
#pragma unroll
    for (int q = 0; q < 4; q++) {
        float v = xr[lane + 32 * q];
        s = fmaf(v, v, s);
    }
#pragma unroll
    for (int o = 16; o; o >>= 1) s += __shfl_xor_sync(0xffffffffu, s, o);
    if (lane == 0) g_sq[row] = s;
}

// ---------------------------------------------------------------------------
// Y = X @ W + b ; also writes the first T rows of the output.
// ---------------------------------------------------------------------------
__global__ void y_kernel(const float* __restrict__ X, const float* __restrict__ W,
                         const float* __restrict__ b, float* __restrict__ out) {
    __shared__ float Ws[D * C];
    int tid = threadIdx.x;
    for (int p = tid; p < D * C; p += 256) Ws[p] = W[p];
    __syncthreads();

    int i = blockIdx.x * 16 + (tid >> 4);
    int c = tid & 15;
    const float* xr = X + i * D;
    float acc = b[c];
#pragma unroll 8
    for (int d = 0; d < D; d++) acc = fmaf(xr[d], Ws[d * C + c], acc);
    g_Y[i * C + c] = acc;
    out[i * C + c] = acc;
}

// ---------------------------------------------------------------------------
// KNN with packed f32x2 FMA.
// Tile: 64 (i) x 128 (j), K-chunks of 32, 256 threads, 4x8 micro-tile.
// A tile stored transposed AND duplicated: As2[k][2*i] = As2[k][2*i+1] = X[i,k]
// so both operands of fma.rn.f32x2 come straight from LDS.128 (no packs).
// v_j = sq_j - 2*dot(x_i,x_j) is rank-equivalent to the reference distance.
// ---------------------------------------------------------------------------
__global__ __launch_bounds__(256) void knn_kernel(const float* __restrict__ X) {
    extern __shared__ float sm[];
    float* As2 = sm;               // [128][128] duplicated A, 64KB
    float* Bs  = sm + 128 * 128;   // [32][128] one K-chunk of B, 16KB
    float* SqJ = Bs + 32 * 128;    // [128]

    int tid = threadIdx.x;
    int tx  = tid & 15;   // j dim
    int ty  = tid >> 4;   // i dim
    int ibase = blockIdx.x * 64;

    // Load + transpose + duplicate A tile (one-time, 64KB of STS)
#pragma unroll
    for (int p = 0; p < 8; p++) {
        int idx = tid + p * 256;
        int row = idx & 63;
        int kc  = idx >> 6;  // 0..31 float4 chunks along D
        float4 v = *(const float4*)(X + (ibase + row) * D + kc * 4);
        *(float2*)&As2[(kc * 4 + 0) * 128 + row * 2] = make_float2(v.x, v.x);
        *(float2*)&As2[(kc * 4 + 1) * 128 + row * 2] = make_float2(v.y, v.y);
        *(float2*)&As2[(kc * 4 + 2) * 128 + row * 2] = make_float2(v.z, v.z);
        *(float2*)&As2[(kc * 4 + 3) * 128 + row * 2] = make_float2(v.w, v.w);
    }

    float v0[4], v1[4];
    int   j0[4], j1[4];
    int   irow[4];
#pragma unroll
    for (int m = 0; m < 4; m++) {
        v0[m] = v1[m] = 3.4e38f;
        j0[m] = j1[m] = 0x7fffffff;
        irow[m] = ibase + ty * 4 + m;
    }

    for (int jt = 0; jt < T / 128; jt++) {
        int jbase = jt * 128;
        u64 accP[4][4];
#pragma unroll
        for (int m = 0; m < 4; m++)
#pragma unroll
            for (int p = 0; p < 4; p++) accP[m][p] = 0ull;

        for (int ch = 0; ch < 4; ch++) {
            __syncthreads();  // previous chunk fully consumed
#pragma unroll
            for (int p = 0; p < 4; p++) {
                int idx = tid + p * 256;
                int row = idx & 127;
                int kc  = idx >> 7;  // 0..7
                float4 v = *(const float4*)(X + (jbase + row) * D + ch * 32 + kc * 4);
                Bs[(kc * 4 + 0) * 128 + row] = v.x;
                Bs[(kc * 4 + 1) * 128 + row] = v.y;
                Bs[(kc * 4 + 2) * 128 + row] = v.z;
                Bs[(kc * 4 + 3) * 128 + row] = v.w;
            }
            if (ch == 0 && tid < 128) SqJ[tid] = g_sq[jbase + tid];
            __syncthreads();

#pragma unroll
            for (int kk = 0; kk < 32; kk++) {
                int k = ch * 32 + kk;
                ulonglong2 aA = *(const ulonglong2*)&As2[k * 128 + ty * 8];
                ulonglong2 aB = *(const ulonglong2*)&As2[k * 128 + ty * 8 + 4];
                ulonglong2 bA = *(const ulonglong2*)&Bs[kk * 128 + tx * 8];
                ulonglong2 bB = *(const ulonglong2*)&Bs[kk * 128 + tx * 8 + 4];
                u64 aP[4] = {aA.x, aA.y, aB.x, aB.y};
                u64 bP[4] = {bA.x, bA.y, bB.x, bB.y};
#pragma unroll
                for (int m = 0; m < 4; m++)
#pragma unroll
                    for (int p = 0; p < 4; p++)
                        accP[m][p] = fma2(aP[m], bP[p], accP[m][p]);
            }
        }

        // top-2 update (exclude self; tie -> lower index, matching top_k)
#pragma unroll
        for (int p = 0; p < 4; p++) {
#pragma unroll
            for (int m = 0; m < 4; m++) {
                float dlo, dhi;
                unpack2(dlo, dhi, accP[m][p]);
#pragma unroll
                for (int h = 0; h < 2; h++) {
                    int   n  = 2 * p + h;
                    int   j  = jbase + tx * 8 + n;
                    float sj = SqJ[tx * 8 + n];
                    float v  = fmaf(-2.f, h ? dhi : dlo, sj);
                    if (j != irow[m]) {
                        if (v < v0[m] || (v == v0[m] && j < j0[m])) {
                            v1[m] = v0[m]; j1[m] = j0[m];
                            v0[m] = v;     j0[m] = j;
                        } else if (v < v1[m] || (v == v1[m] && j < j1[m])) {
                            v1[m] = v;     j1[m] = j;
                        }
                    }
                }
            }
        }
    }

    // Cross-thread merge (16 tx threads per row, 2 candidates each).
    __syncthreads();
    float* candV = sm;               // 64*32 floats
    int*   candI = (int*)(sm + 64 * 32);
#pragma unroll
    for (int m = 0; m < 4; m++) {
        int row = ty * 4 + m;
        candV[row * 32 + tx * 2]     = v0[m];
        candV[row * 32 + tx * 2 + 1] = v1[m];
        candI[row * 32 + tx * 2]     = j0[m];
        candI[row * 32 + tx * 2 + 1] = j1[m];
    }
    __syncthreads();
    if (tid < 64) {
        float b0v = 3.4e38f, b1v = 3.4e38f;
        int   b0i = 0x7fffffff, b1i = 0x7fffffff;
        for (int q = 0; q < 32; q++) {
            float v  = candV[tid * 32 + q];
            int   jj = candI[tid * 32 + q];
            if (v < b0v || (v == b0v && jj < b0i)) {
                b1v = b0v; b1i = b0i; b0v = v; b0i = jj;
            } else if (v < b1v || (v == b1v && jj < b1i)) {
                b1v = v; b1i = jj;
            }
        }
        g_nbr[(ibase + tid) * 2]     = b0i;
        g_nbr[(ibase + tid) * 2 + 1] = b1i;
    }
}

// ---------------------------------------------------------------------------
// Synthetic rows in logit space (linearity of W):
// out[T+s] = Y[src] + gaps[s] * (Y[chosen] - Y[src])
// ---------------------------------------------------------------------------
__global__ void syn_kernel(const int* __restrict__ nn_idx,
                           const float* __restrict__ gaps,
                           float* __restrict__ out) {
    int idx = blockIdx.x * 256 + threadIdx.x;
    int s   = idx >> 4;
    int c   = idx & 15;
    int src = s >> 2;
    int k   = nn_idx[s] & 1;
    int ch  = g_nbr[src * 2 + k];
    float g  = gaps[s];
    float ys = g_Y[src * C + c];
    float yc = g_Y[ch * C + c];
    out[(T + s) * C + c] = ys + g * (yc - ys);
}

// ---------------------------------------------------------------------------
extern "C" void kernel_launch(void* const* d_in, const int* in_sizes, int n_in,
                              void* d_out, int out_size) {
    const float* X      = (const float*)d_in[0];
    const int*   nn_idx = (const int*)d_in[1];
    const float* gaps   = (const float*)d_in[2];
    const float* W      = (const float*)d_in[3];
    const float* b      = (const float*)d_in[4];
    float* out = (float*)d_out;

    const int KNN_SMEM = (128 * 128 + 32 * 128 + 128) * (int)sizeof(float);
    cudaFuncSetAttribute(knn_kernel, cudaFuncAttributeMaxDynamicSharedMemorySize,
                         KNN_SMEM);

    sq_kernel <<<T / 8,  256>>>(X);
    y_kernel  <<<T / 16, 256>>>(X, W, b, out);
    knn_kernel<<<T / 64, 256, KNN_SMEM>>>(X);
    syn_kernel<<<NM * T * C / 256, 256>>>(nn_idx, gaps, out);
}

// round 13
// speedup vs baseline: 2.0951x; 2.0536x over previous
#include <cuda_runtime.h>
#include <cuda_bf16.h>
#include <cstdint>

#define T 8192
#define D 128
#define C 16
#define NM 4

typedef unsigned long long u64;
typedef unsigned int u32;

// ---- device scratch (no allocations allowed) ----
__device__ float g_sq[T];
__device__ float g_Y[T * C];
__device__ int   g_nbr[T * 2];
__device__ __nv_bfloat16 g_E[T * 384];   // [h | m | l] bf16 split, 6MB
__device__ u64   g_cand[T * 8 * 2];      // per-row, per-j-octant top-2 keys

// monotone float->u32 flip; key = (flip(v)<<32)|j : min key == min v, tie -> lower j
__device__ __forceinline__ u64 pack_key(float v, int j) {
    u32 f = __float_as_uint(v);
    f ^= (u32)((int)f >> 31) | 0x80000000u;
    return ((u64)f << 32) | (u32)j;
}

// merge candidate pair (t0<=t1) into running pair (s0<=s1)
__device__ __forceinline__ void merge2(u64& s0, u64& s1, u64 t0, u64 t1) {
    u64 lo = t0 < s0 ? t0 : s0;
    u64 hi = t0 < s0 ? s0 : t0;
    u64 m1 = t1 < s1 ? t1 : s1;
    s1 = hi < m1 ? hi : m1;
    s0 = lo;
}

// m16n8k16 bf16 MMA (sm_80+; no arch-'a' gating)
__device__ __forceinline__ void mma_bf16(float* d, const u32* a, const u32* b) {
    asm volatile(
        "mma.sync.aligned.m16n8k16.row.col.f32.bf16.bf16.f32 "
        "{%0,%1,%2,%3}, {%4,%5,%6,%7}, {%8,%9}, {%0,%1,%2,%3};"
        : "+f"(d[0]), "+f"(d[1]), "+f"(d[2]), "+f"(d[3])
        : "r"(a[0]), "r"(a[1]), "r"(a[2]), "r"(a[3]), "r"(b[0]), "r"(b[1]));
}

// ---------------------------------------------------------------------------
// 3-way bf16 split: x = h + m + l. E[i] = [h(128) | m(128) | l(128)].
// A-chunks h,m,h,m,l,h vs B-chunks h,h,m,m,h,l -> dot error ~2e-7 (recall only;
// final ranking is re-done by refine_kernel with R2's exact fp32 comparator).
// ---------------------------------------------------------------------------
__global__ void split_kernel(const float* __restrict__ X) {
    int i   = blockIdx.x * 256 + threadIdx.x;   // over T*D/4
    int row = i >> 5;
    int kq  = (i & 31) * 4;
    float4 v = ((const float4*)X)[i];
    float xs[4] = {v.x, v.y, v.z, v.w};
    __nv_bfloat16 h[4], m[4], l[4];
#pragma unroll
    for (int q = 0; q < 4; q++) {
        float x = xs[q];
        h[q] = __float2bfloat16(x);
        float r1 = x - __bfloat162float(h[q]);
        m[q] = __float2bfloat16(r1);
        float r2 = r1 - __bfloat162float(m[q]);
        l[q] = __float2bfloat16(r2);
    }
    *(uint2*)&g_E[row * 384 + kq]       = *(uint2*)h;
    *(uint2*)&g_E[row * 384 + 128 + kq] = *(uint2*)m;
    *(uint2*)&g_E[row * 384 + 256 + kq] = *(uint2*)l;
}

// ---------------------------------------------------------------------------
__global__ void sq_kernel(const float* __restrict__ X) {
    int row  = blockIdx.x * 8 + (threadIdx.x >> 5);
    int lane = threadIdx.x & 31;
    const float* xr = X + row * D;
    float s = 0.f;
#pragma unroll
    for (int q = 0; q < 4; q++) {
        float v = xr[lane + 32 * q];
        s = fmaf(v, v, s);
    }
#pragma unroll
    for (int o = 16; o; o >>= 1) s += __shfl_xor_sync(0xffffffffu, s, o);
    if (lane == 0) g_sq[row] = s;
}

// ---------------------------------------------------------------------------
__global__ void y_kernel(const float* __restrict__ X, const float* __restrict__ W,
                         const float* __restrict__ b, float* __restrict__ out) {
    __shared__ float Ws[D * C];
    int tid = threadIdx.x;
    for (int p = tid; p < D * C; p += 256) Ws[p] = W[p];
    __syncthreads();
    int i = blockIdx.x * 16 + (tid >> 4);
    int c = tid & 15;
    const float* xr = X + i * D;
    float acc = b[c];
#pragma unroll 8
    for (int d = 0; d < D; d++) acc = fmaf(xr[d], Ws[d * C + c], acc);
    g_Y[i * C + c] = acc;
    out[i * C + c] = acc;
}

// ---------------------------------------------------------------------------
// KNN candidate GEMM via m16n8k16 bf16 HMMA, top-2 per j-octant per row.
// CTA: 128(i) x 128(j), K_ext=768 bf16 in 6 chunks of 128.
// 8 warps = 2(m) x 4(n), warp tile 64x32. grid = 64 i-tiles x 8 j-octants.
// ---------------------------------------------------------------------------
#define SA 68                                  // u32 stride per smem row
#define BS_OFF  (128 * SA * 4)                 // 34816
#define SQ_OFF  (2 * 128 * SA * 4)             // 69632
#define CD_OFF  (SQ_OFF + 512)                 // 70144
#define KNN_SMEM (CD_OFF + 128 * 4 * 16)       // 78336

__global__ __launch_bounds__(256, 2) void knn_mma_kernel() {
    extern __shared__ char smraw[];
    u32*   As   = (u32*)smraw;
    u32*   Bs   = (u32*)(smraw + BS_OFF);
    float* sSq  = (float*)(smraw + SQ_OFF);
    u64*   scnd = (u64*)(smraw + CD_OFF);      // [128 rows][4 warp_n][2]

    const int tid  = threadIdx.x;
    const int wid  = tid >> 5;
    const int lane = tid & 31;
    const int g    = lane >> 2;                // group id 0..7
    const int cq   = lane & 3;                 // quad lane 0..3
    const int warp_m = wid >> 2;               // 0..1
    const int warp_n = wid & 3;                // 0..3
    const int itile  = blockIdx.x >> 3;        // 0..63
    const int jq     = blockIdx.x & 7;         // 0..7

    for (int p = tid; p < 128 * 4 * 2; p += 256) scnd[p] = ~0ull;

    const int ldrow = tid >> 4;                // 16 threads/row, 1 uint4 each
    const int ldkb  = (tid & 15) * 8;          // bf16 col offset (8 bf16 = 16B)

    // per-128-chunk bf16 column offsets into E's 384 cols (h=0, m=128, l=256)
    const int aoff[6] = {0, 128, 0, 128, 256, 0};     // h m h m l h
    const int boff[6] = {0, 0, 128, 128, 0, 256};     // h h m m h l

    for (int jt = 0; jt < 8; jt++) {
        const int jbase = (jq * 8 + jt) * 128;
        float acc[4][4][4];
#pragma unroll
        for (int mt = 0; mt < 4; mt++)
#pragma unroll
            for (int nt = 0; nt < 4; nt++)
#pragma unroll
                for (int q = 0; q < 4; q++) acc[mt][nt][q] = 0.f;

        for (int kc = 0; kc < 6; kc++) {
            __syncthreads();
#pragma unroll
            for (int p = 0; p < 8; p++) {
                int r = ldrow + p * 16;
                *(uint4*)(As + r * SA + (ldkb >> 1)) =
                    *(const uint4*)(g_E + (itile * 128 + r) * 384 + aoff[kc] + ldkb);
                *(uint4*)(Bs + r * SA + (ldkb >> 1)) =
                    *(const uint4*)(g_E + (jbase + r) * 384 + boff[kc] + ldkb);
            }
            if (kc == 0 && tid < 128) sSq[tid] = g_sq[jbase + tid];
            __syncthreads();

#pragma unroll
            for (int k16 = 0; k16 < 8; k16++) {
                u32 af[4][4], bf[4][2];
#pragma unroll
                for (int mt = 0; mt < 4; mt++) {
                    const u32* ba = As + (warp_m * 64 + mt * 16 + g) * SA + k16 * 8 + cq;
                    af[mt][0] = ba[0];
                    af[mt][1] = ba[8 * SA];
                    af[mt][2] = ba[4];
                    af[mt][3] = ba[8 * SA + 4];
                }
#pragma unroll
                for (int nt = 0; nt < 4; nt++) {
                    const u32* bb = Bs + (warp_n * 32 + nt * 8 + g) * SA + k16 * 8 + cq;
                    bf[nt][0] = bb[0];
                    bf[nt][1] = bb[4];
                }
#pragma unroll
                for (int mt = 0; mt < 4; mt++)
#pragma unroll
                    for (int nt = 0; nt < 4; nt++)
                        mma_bf16(acc[mt][nt], af[mt], bf[nt]);
            }
        }

        // ---- fused top-2 epilogue (candidate recall): v = sq_j - 2*dot ----
#pragma unroll
        for (int mt = 0; mt < 4; mt++)
#pragma unroll
            for (int h = 0; h < 2; h++) {
                int rloc = warp_m * 64 + mt * 16 + g + h * 8;    // 0..127
                int irow = itile * 128 + rloc;
                u64 t0 = ~0ull, t1 = ~0ull;
#pragma unroll
                for (int nt = 0; nt < 4; nt++)
#pragma unroll
                    for (int q = 0; q < 2; q++) {
                        int cloc = warp_n * 32 + nt * 8 + 2 * cq + q;
                        int j = jbase + cloc;
                        float v = fmaf(-2.f, acc[mt][nt][h * 2 + q], sSq[cloc]);
                        if (j != irow) {
                            u64 key = pack_key(v, j);
                            if (key < t0) { t1 = t0; t0 = key; }
                            else if (key < t1) t1 = key;
                        }
                    }
                // butterfly merge across the quad (lanes differing in cq)
#pragma unroll
                for (int o = 1; o <= 2; o <<= 1) {
                    u64 o0 = __shfl_xor_sync(0xffffffffu, t0, o);
                    u64 o1 = __shfl_xor_sync(0xffffffffu, t1, o);
                    merge2(t0, t1, o0, o1);
                }
                if (cq == 0) {
                    u64* slot = &scnd[(rloc * 4 + warp_n) * 2];
                    u64 s0 = slot[0], s1 = slot[1];
                    merge2(s0, s1, t0, t1);
                    slot[0] = s0; slot[1] = s1;
                }
            }
    }

    __syncthreads();
    if (tid < 128) {
        u64 b0 = ~0ull, b1 = ~0ull;
#pragma unroll
        for (int q = 0; q < 8; q++) {
            u64 k = scnd[tid * 8 + q];
            if (k < b0) { b1 = b0; b0 = k; }
            else if (k < b1) b1 = k;
        }
        int ig = itile * 128 + tid;
        g_cand[(ig * 8 + jq) * 2 + 0] = b0;
        g_cand[(ig * 8 + jq) * 2 + 1] = b1;
    }
}

// ---------------------------------------------------------------------------
// Refinement: re-rank the 16 octant candidates per row using EXACTLY the
// comparator of the R2 kernel that passed: v = sq_j - 2*dot(x_i,x_j) with a
// single-accumulator sequential fp32 fmaf over k=0..127 (error statistics
// correlated with the reference's fp32 matmul), tie -> lower index.
// 16 threads per row (one per candidate), shuffle top-2 reduction.
// ---------------------------------------------------------------------------
__global__ void refine_kernel(const float* __restrict__ X) {
    int tid = threadIdx.x;
    int row = blockIdx.x * 16 + (tid >> 4);
    int c   = tid & 15;
    u32 j   = (u32)g_cand[row * 16 + c];
    u64 k2  = ~0ull;
    if (j < T) {
        const float* xi = X + row * D;
        const float* xj = X + j * D;
        float acc = 0.f;
#pragma unroll 16
        for (int k = 0; k < D; k++) acc = fmaf(xi[k], xj[k], acc);
        float v = g_sq[j] - 2.0f * acc;
        k2 = pack_key(v, (int)j);
    }
    u64 t0 = k2, t1 = ~0ull;
#pragma unroll
    for (int o = 1; o < 16; o <<= 1) {   // stays within the 16-lane row group
        u64 o0 = __shfl_xor_sync(0xffffffffu, t0, o);
        u64 o1 = __shfl_xor_sync(0xffffffffu, t1, o);
        merge2(t0, t1, o0, o1);
    }
    if (c == 0) {
        g_nbr[row * 2 + 0] = (int)(u32)t0;
        g_nbr[row * 2 + 1] = (int)(u32)t1;
    }
}

// ---------------------------------------------------------------------------
__global__ void syn_kernel(const int* __restrict__ nn_idx,
                           const float* __restrict__ gaps,
                           float* __restrict__ out) {
    int idx = blockIdx.x * 256 + threadIdx.x;
    int s   = idx >> 4;
    int c   = idx & 15;
    int src = s >> 2;
    int k   = nn_idx[s] & 1;
    int ch  = g_nbr[src * 2 + k];
    float g  = gaps[s];
    float ys = g_Y[src * C + c];
    float yc = g_Y[ch * C + c];
    out[(T + s) * C + c] = ys + g * (yc - ys);
}

// ---------------------------------------------------------------------------
extern "C" void kernel_launch(void* const* d_in, const int* in_sizes, int n_in,
                              void* d_out, int out_size) {
    const float* X      = (const float*)d_in[0];
    const int*   nn_idx = (const int*)d_in[1];
    const float* gaps   = (const float*)d_in[2];
    const float* W      = (const float*)d_in[3];
    const float* b      = (const float*)d_in[4];
    float* out = (float*)d_out;

    cudaFuncSetAttribute(knn_mma_kernel,
                         cudaFuncAttributeMaxDynamicSharedMemorySize, KNN_SMEM);

    split_kernel  <<<T * D / 4 / 256, 256>>>(X);
    sq_kernel     <<<T / 8,  256>>>(X);
    y_kernel      <<<T / 16, 256>>>(X, W, b, out);
    knn_mma_kernel<<<64 * 8, 256, KNN_SMEM>>>();
    refine_kernel <<<T / 16, 256>>>(X);
    syn_kernel    <<<NM * T * C / 256, 256>>>(nn_idx, gaps, out);
}

// round 14
// speedup vs baseline: 2.1732x; 1.0373x over previous
#include <cuda_runtime.h>
#include <cuda_bf16.h>
#include <cstdint>

#define T 8192
#define D 128
#define C 16
#define NM 4

typedef unsigned long long u64;
typedef unsigned int u32;

// ---- device scratch (no allocations allowed) ----
__device__ float g_sq[T];
__device__ float g_Y[T * C];
__device__ int   g_nbr[T * 2];
__device__ __nv_bfloat16 g_E[T * 384];   // [h | m | l] bf16 split, 6MB
__device__ u64   g_cand[T * 8 * 2];      // per-row, per-j-octant top-2 keys

// 64-col chunk offsets into E's 384 cols, derived from the (proven) 128-col
// sequences A: h,m,h,m,l,h  B: h,h,m,m,h,l  (each 128-chunk split in half,
// preserving the exact MMA accumulation k-order of the passing R13 kernel).
__device__ const int g_aoff64[12] = {0,64, 128,192, 0,64, 128,192, 256,320, 0,64};
__device__ const int g_boff64[12] = {0,64, 0,64, 128,192, 128,192, 0,64, 256,320};

// monotone float->u32 flip; key = (flip(v)<<32)|j : min key == min v, tie -> lower j
__device__ __forceinline__ u64 pack_key(float v, int j) {
    u32 f = __float_as_uint(v);
    f ^= (u32)((int)f >> 31) | 0x80000000u;
    return ((u64)f << 32) | (u32)j;
}

// merge candidate pair (t0<=t1) into running pair (s0<=s1)
__device__ __forceinline__ void merge2(u64& s0, u64& s1, u64 t0, u64 t1) {
    u64 lo = t0 < s0 ? t0 : s0;
    u64 hi = t0 < s0 ? s0 : t0;
    u64 m1 = t1 < s1 ? t1 : s1;
    s1 = hi < m1 ? hi : m1;
    s0 = lo;
}

__device__ __forceinline__ u32 smem_u32(const void* p) {
    u32 a;
    asm("{ .reg .u64 t; cvta.to.shared.u64 t, %1; cvt.u32.u64 %0, t; }"
        : "=r"(a) : "l"(p));
    return a;
}

// m16n8k16 bf16 MMA (sm_80+; no arch-'a' gating)
__device__ __forceinline__ void mma_bf16(float* d, const u32* a, const u32* b) {
    asm volatile(
        "mma.sync.aligned.m16n8k16.row.col.f32.bf16.bf16.f32 "
        "{%0,%1,%2,%3}, {%4,%5,%6,%7}, {%8,%9}, {%0,%1,%2,%3};"
        : "+f"(d[0]), "+f"(d[1]), "+f"(d[2]), "+f"(d[3])
        : "r"(a[0]), "r"(a[1]), "r"(a[2]), "r"(a[3]), "r"(b[0]), "r"(b[1]));
}

__device__ __forceinline__ void ldmx4(u32& r0, u32& r1, u32& r2, u32& r3, u32 a) {
    asm volatile("ldmatrix.sync.aligned.m8n8.x4.shared.b16 {%0,%1,%2,%3}, [%4];"
                 : "=r"(r0), "=r"(r1), "=r"(r2), "=r"(r3) : "r"(a));
}
__device__ __forceinline__ void ldmx2(u32& r0, u32& r1, u32 a) {
    asm volatile("ldmatrix.sync.aligned.m8n8.x2.shared.b16 {%0,%1}, [%2];"
                 : "=r"(r0), "=r"(r1) : "r"(a));
}

__device__ __forceinline__ void cp16(u32 dst, const __nv_bfloat16* src) {
    asm volatile("cp.async.cg.shared.global [%0], [%1], 16;"
                 :: "r"(dst), "l"(src) : "memory");
}
#define CP_COMMIT() asm volatile("cp.async.commit_group;" ::: "memory")
#define CP_WAIT1()  asm volatile("cp.async.wait_group 1;"  ::: "memory")

// ---------------------------------------------------------------------------
// 3-way bf16 split (unchanged from R13)
// ---------------------------------------------------------------------------
__global__ void split_kernel(const float* __restrict__ X) {
    int i   = blockIdx.x * 256 + threadIdx.x;   // over T*D/4
    int row = i >> 5;
    int kq  = (i & 31) * 4;
    float4 v = ((const float4*)X)[i];
    float xs[4] = {v.x, v.y, v.z, v.w};
    __nv_bfloat16 h[4], m[4], l[4];
#pragma unroll
    for (int q = 0; q < 4; q++) {
        float x = xs[q];
        h[q] = __float2bfloat16(x);
        float r1 = x - __bfloat162float(h[q]);
        m[q] = __float2bfloat16(r1);
        float r2 = r1 - __bfloat162float(m[q]);
        l[q] = __float2bfloat16(r2);
    }
    *(uint2*)&g_E[row * 384 + kq]       = *(uint2*)h;
    *(uint2*)&g_E[row * 384 + 128 + kq] = *(uint2*)m;
    *(uint2*)&g_E[row * 384 + 256 + kq] = *(uint2*)l;
}

// ---------------------------------------------------------------------------
__global__ void sq_kernel(const float* __restrict__ X) {
    int row  = blockIdx.x * 8 + (threadIdx.x >> 5);
    int lane = threadIdx.x & 31;
    const float* xr = X + row * D;
    float s = 0.f;
#pragma unroll
    for (int q = 0; q < 4; q++) {
        float v = xr[lane + 32 * q];
        s = fmaf(v, v, s);
    }
#pragma unroll
    for (int o = 16; o; o >>= 1) s += __shfl_xor_sync(0xffffffffu, s, o);
    if (lane == 0) g_sq[row] = s;
}

// ---------------------------------------------------------------------------
__global__ void y_kernel(const float* __restrict__ X, const float* __restrict__ W,
                         const float* __restrict__ b, float* __restrict__ out) {
    __shared__ float Ws[D * C];
    int tid = threadIdx.x;
    for (int p = tid; p < D * C; p += 256) Ws[p] = W[p];
    __syncthreads();
    int i = blockIdx.x * 16 + (tid >> 4);
    int c = tid & 15;
    const float* xr = X + i * D;
    float acc = b[c];
#pragma unroll 8
    for (int d = 0; d < D; d++) acc = fmaf(xr[d], Ws[d * C + c], acc);
    g_Y[i * C + c] = acc;
    out[i * C + c] = acc;
}

// ---------------------------------------------------------------------------
// KNN candidate GEMM, pipelined:
// CTA 128(i) x 128(j), 128 threads = 4 warps (2m x 2n), warp tile 64x64.
// K chunks of 64 bf16 (12 stages/jt), A+B cp.async double-buffered,
// ldmatrix fragment loads. Epilogue/comparators identical to R13.
// smem buffer: [128 rows][36 u32] (64 bf16 + pad), stride 144B (conflict-free:
// bank step 4 per row -> 8 ldmatrix rows cover 32 banks).
// ---------------------------------------------------------------------------
#define BUFB   18432                          // 128 * 144
#define B_OFF  36864                          // A0,A1 then B0,B1
#define SQ_OFF 73728
#define CD_OFF 74240
#define KNN_SMEM (CD_OFF + 128 * 2 * 16)      // 78336

__device__ __forceinline__ void issue_stage(u32 smb, int stage, int irow0,
                                            int jbase, int tid) {
    int ao  = g_aoff64[stage];
    int bo  = g_boff64[stage];
    u32 dA  = smb + (stage & 1) * BUFB;
    u32 dB  = smb + B_OFF + (stage & 1) * BUFB;
    const __nv_bfloat16* eA = g_E + irow0 * 384 + ao;
    const __nv_bfloat16* eB = g_E + jbase * 384 + bo;
#pragma unroll
    for (int p = 0; p < 8; p++) {
        int s   = tid + p * 128;
        int row = s >> 3, c16 = s & 7;
        cp16(dA + row * 144 + c16 * 16, eA + row * 384 + c16 * 8);
        cp16(dB + row * 144 + c16 * 16, eB + row * 384 + c16 * 8);
    }
}

__global__ __launch_bounds__(128, 2) void knn_mma_kernel() {
    extern __shared__ char smraw[];
    const u32 smb = smem_u32(smraw);
    float* sSq  = (float*)(smraw + SQ_OFF);
    u64*   scnd = (u64*)(smraw + CD_OFF);      // [128 rows][2 warp_n][2]

    const int tid  = threadIdx.x;
    const int wid  = tid >> 5;
    const int lane = tid & 31;
    const int g    = lane >> 2;
    const int cq   = lane & 3;
    const int warp_m = wid >> 1;               // 0..1
    const int warp_n = wid & 1;                // 0..1
    const int itile  = blockIdx.x >> 3;        // 0..63
    const int jq     = blockIdx.x & 7;         // 0..7
    const int irow0  = itile * 128;

    for (int p = tid; p < 128 * 2 * 2; p += 128) scnd[p] = ~0ull;

    // per-lane ldmatrix address bases
    const u32 aBase = smb + (warp_m * 64 + (lane & 15)) * 144 + (lane >> 4) * 16;
    const u32 bBase = smb + B_OFF + (warp_n * 64 + (lane & 7)) * 144
                      + ((lane >> 3) & 1) * 16;

    for (int jt = 0; jt < 8; jt++) {
        const int jbase = (jq * 8 + jt) * 128;
        __syncthreads();                       // prev epilogue done (sSq reads)
        issue_stage(smb, 0, irow0, jbase, tid); CP_COMMIT();
        issue_stage(smb, 1, irow0, jbase, tid); CP_COMMIT();
        if (tid < 128) sSq[tid] = g_sq[jbase + tid];

        float acc[4][8][4];
#pragma unroll
        for (int mt = 0; mt < 4; mt++)
#pragma unroll
            for (int nt = 0; nt < 8; nt++)
#pragma unroll
                for (int q = 0; q < 4; q++) acc[mt][nt][q] = 0.f;

#pragma unroll 1
        for (int kc = 0; kc < 12; kc++) {
            CP_WAIT1();
            __syncthreads();                   // stage kc resident everywhere
            u32 bufo = (u32)(kc & 1) * BUFB;
#pragma unroll
            for (int k16 = 0; k16 < 4; k16++) {
                u32 af[4][4], bf[8][2];
#pragma unroll
                for (int mt = 0; mt < 4; mt++)
                    ldmx4(af[mt][0], af[mt][1], af[mt][2], af[mt][3],
                          aBase + bufo + mt * 2304 + k16 * 32);
#pragma unroll
                for (int nt = 0; nt < 8; nt++)
                    ldmx2(bf[nt][0], bf[nt][1],
                          bBase + bufo + nt * 1152 + k16 * 32);
#pragma unroll
                for (int mt = 0; mt < 4; mt++)
#pragma unroll
                    for (int nt = 0; nt < 8; nt++)
                        mma_bf16(acc[mt][nt], af[mt], bf[nt]);
            }
            __syncthreads();                   // reads of buf done -> may refill
            if (kc < 10) issue_stage(smb, kc + 2, irow0, jbase, tid);
            CP_COMMIT();                       // keep group count consistent
        }

        // ---- fused top-2 epilogue (recall): v = sq_j - 2*dot (as in R13) ----
#pragma unroll
        for (int mt = 0; mt < 4; mt++)
#pragma unroll
            for (int h = 0; h < 2; h++) {
                int rloc = warp_m * 64 + mt * 16 + g + h * 8;    // 0..127
                int irow = irow0 + rloc;
                u64 t0 = ~0ull, t1 = ~0ull;
#pragma unroll
                for (int nt = 0; nt < 8; nt++)
#pragma unroll
                    for (int q = 0; q < 2; q++) {
                        int cloc = warp_n * 64 + nt * 8 + 2 * cq + q;
                        int j = jbase + cloc;
                        float v = fmaf(-2.f, acc[mt][nt][h * 2 + q], sSq[cloc]);
                        if (j != irow) {
                            u64 key = pack_key(v, j);
                            if (key < t0) { t1 = t0; t0 = key; }
                            else if (key < t1) t1 = key;
                        }
                    }
#pragma unroll
                for (int o = 1; o <= 2; o <<= 1) {
                    u64 o0 = __shfl_xor_sync(0xffffffffu, t0, o);
                    u64 o1 = __shfl_xor_sync(0xffffffffu, t1, o);
                    merge2(t0, t1, o0, o1);
                }
                if (cq == 0) {
                    u64* slot = &scnd[(rloc * 2 + warp_n) * 2];
                    u64 s0 = slot[0], s1 = slot[1];
                    merge2(s0, s1, t0, t1);
                    slot[0] = s0; slot[1] = s1;
                }
            }
    }

    __syncthreads();
    if (tid < 128) {
        u64 b0 = ~0ull, b1 = ~0ull;
#pragma unroll
        for (int q = 0; q < 4; q++) {
            u64 k = scnd[tid * 4 + q];
            if (k < b0) { b1 = b0; b0 = k; }
            else if (k < b1) b1 = k;
        }
        int ig = irow0 + tid;
        g_cand[(ig * 8 + jq) * 2 + 0] = b0;
        g_cand[(ig * 8 + jq) * 2 + 1] = b1;
    }
}

// ---------------------------------------------------------------------------
// Refinement with EXACTLY the R2 comparator (unchanged from R13)
// ---------------------------------------------------------------------------
__global__ void refine_kernel(const float* __restrict__ X) {
    int tid = threadIdx.x;
    int row = blockIdx.x * 16 + (tid >> 4);
    int c   = tid & 15;
    u32 j   = (u32)g_cand[row * 16 + c];
    u64 k2  = ~0ull;
    if (j < T) {
        const float* xi = X + row * D;
        const float* xj = X + j * D;
        float acc = 0.f;
#pragma unroll 16
        for (int k = 0; k < D; k++) acc = fmaf(xi[k], xj[k], acc);
        float v = g_sq[j] - 2.0f * acc;
        k2 = pack_key(v, (int)j);
    }
    u64 t0 = k2, t1 = ~0ull;
#pragma unroll
    for (int o = 1; o < 16; o <<= 1) {
        u64 o0 = __shfl_xor_sync(0xffffffffu, t0, o);
        u64 o1 = __shfl_xor_sync(0xffffffffu, t1, o);
        merge2(t0, t1, o0, o1);
    }
    if (c == 0) {
        g_nbr[row * 2 + 0] = (int)(u32)t0;
        g_nbr[row * 2 + 1] = (int)(u32)t1;
    }
}

// ---------------------------------------------------------------------------
__global__ void syn_kernel(const int* __restrict__ nn_idx,
                           const float* __restrict__ gaps,
                           float* __restrict__ out) {
    int idx = blockIdx.x * 256 + threadIdx.x;
    int s   = idx >> 4;
    int c   = idx & 15;
    int src = s >> 2;
    int k   = nn_idx[s] & 1;
    int ch  = g_nbr[src * 2 + k];
    float g  = gaps[s];
    float ys = g_Y[src * C + c];
    float yc = g_Y[ch * C + c];
    out[(T + s) * C + c] = ys + g * (yc - ys);
}

// ---------------------------------------------------------------------------
extern "C" void kernel_launch(void* const* d_in, const int* in_sizes, int n_in,
                              void* d_out, int out_size) {
    const float* X      = (const float*)d_in[0];
    const int*   nn_idx = (const int*)d_in[1];
    const float* gaps   = (const float*)d_in[2];
    const float* W      = (const float*)d_in[3];
    const float* b      = (const float*)d_in[4];
    float* out = (float*)d_out;

    cudaFuncSetAttribute(knn_mma_kernel,
                         cudaFuncAttributeMaxDynamicSharedMemorySize, KNN_SMEM);

    split_kernel  <<<T * D / 4 / 256, 256>>>(X);
    sq_kernel     <<<T / 8,  256>>>(X);
    y_kernel      <<<T / 16, 256>>>(X, W, b, out);
    knn_mma_kernel<<<64 * 8, 128, KNN_SMEM>>>();
    refine_kernel <<<T / 16, 256>>>(X);
    syn_kernel    <<<NM * T * C / 256, 256>>>(nn_idx, gaps, out);
}

// round 15
// speedup vs baseline: 2.4514x; 1.1280x over previous
#include <cuda_runtime.h>
#include <cuda_bf16.h>
#include <cstdint>

#define T 8192
#define D 128
#define C 16
#define NM 4

typedef unsigned long long u64;
typedef unsigned int u32;

// ---- device scratch (no allocations allowed) ----
__device__ float g_sq[T];
__device__ float g_Y[T * C];
__device__ int   g_nbr[T * 2];
__device__ __nv_bfloat16 g_E[T * 384];   // [h | m | l] bf16 split, 6MB
__device__ u64   g_cand[T * 8 * 2];      // per-row, per-j-octant top-2 keys

// 64-col stage offsets into E's 384 cols (A: h,m,h,m,l,h ; B: h,h,m,m,h,l
// in 128-col pairs — same k-order as the passing R13/R14 kernels).
__device__ const int g_aoff64[12] = {0,64, 128,192, 0,64, 128,192, 256,320, 0,64};
__device__ const int g_boff64[12] = {0,64, 0,64, 128,192, 128,192, 0,64, 256,320};

__device__ __forceinline__ u64 pack_key(float v, int j) {
    u32 f = __float_as_uint(v);
    f ^= (u32)((int)f >> 31) | 0x80000000u;
    return ((u64)f << 32) | (u32)j;
}

__device__ __forceinline__ void merge2(u64& s0, u64& s1, u64 t0, u64 t1) {
    u64 lo = t0 < s0 ? t0 : s0;
    u64 hi = t0 < s0 ? s0 : t0;
    u64 m1 = t1 < s1 ? t1 : s1;
    s1 = hi < m1 ? hi : m1;
    s0 = lo;
}

__device__ __forceinline__ u32 smem_u32(const void* p) {
    u32 a;
    asm("{ .reg .u64 t; cvta.to.shared.u64 t, %1; cvt.u32.u64 %0, t; }"
        : "=r"(a) : "l"(p));
    return a;
}

__device__ __forceinline__ void mma_bf16(float* d, const u32* a, const u32* b) {
    asm volatile(
        "mma.sync.aligned.m16n8k16.row.col.f32.bf16.bf16.f32 "
        "{%0,%1,%2,%3}, {%4,%5,%6,%7}, {%8,%9}, {%0,%1,%2,%3};"
        : "+f"(d[0]), "+f"(d[1]), "+f"(d[2]), "+f"(d[3])
        : "r"(a[0]), "r"(a[1]), "r"(a[2]), "r"(a[3]), "r"(b[0]), "r"(b[1]));
}

__device__ __forceinline__ void ldmx4(u32& r0, u32& r1, u32& r2, u32& r3, u32 a) {
    asm volatile("ldmatrix.sync.aligned.m8n8.x4.shared.b16 {%0,%1,%2,%3}, [%4];"
                 : "=r"(r0), "=r"(r1), "=r"(r2), "=r"(r3) : "r"(a));
}
__device__ __forceinline__ void ldmx2(u32& r0, u32& r1, u32 a) {
    asm volatile("ldmatrix.sync.aligned.m8n8.x2.shared.b16 {%0,%1}, [%2];"
                 : "=r"(r0), "=r"(r1) : "r"(a));
}

__device__ __forceinline__ void cp16(u32 dst, const __nv_bfloat16* src) {
    asm volatile("cp.async.cg.shared.global [%0], [%1], 16;"
                 :: "r"(dst), "l"(src) : "memory");
}
#define CP_COMMIT() asm volatile("cp.async.commit_group;" ::: "memory")
#define CP_WAIT1()  asm volatile("cp.async.wait_group 1;"  ::: "memory")

// ---------------------------------------------------------------------------
__global__ void split_kernel(const float* __restrict__ X) {
    int i   = blockIdx.x * 256 + threadIdx.x;
    int row = i >> 5;
    int kq  = (i & 31) * 4;
    float4 v = ((const float4*)X)[i];
    float xs[4] = {v.x, v.y, v.z, v.w};
    __nv_bfloat16 h[4], m[4], l[4];
#pragma unroll
    for (int q = 0; q < 4; q++) {
        float x = xs[q];
        h[q] = __float2bfloat16(x);
        float r1 = x - __bfloat162float(h[q]);
        m[q] = __float2bfloat16(r1);
        float r2 = r1 - __bfloat162float(m[q]);
        l[q] = __float2bfloat16(r2);
    }
    *(uint2*)&g_E[row * 384 + kq]       = *(uint2*)h;
    *(uint2*)&g_E[row * 384 + 128 + kq] = *(uint2*)m;
    *(uint2*)&g_E[row * 384 + 256 + kq] = *(uint2*)l;
}

// ---------------------------------------------------------------------------
__global__ void sq_kernel(const float* __restrict__ X) {
    int row  = blockIdx.x * 8 + (threadIdx.x >> 5);
    int lane = threadIdx.x & 31;
    const float* xr = X + row * D;
    float s = 0.f;
#pragma unroll
    for (int q = 0; q < 4; q++) {
        float v = xr[lane + 32 * q];
        s = fmaf(v, v, s);
    }
#pragma unroll
    for (int o = 16; o; o >>= 1) s += __shfl_xor_sync(0xffffffffu, s, o);
    if (lane == 0) g_sq[row] = s;
}

// ---------------------------------------------------------------------------
__global__ void y_kernel(const float* __restrict__ X, const float* __restrict__ W,
                         const float* __restrict__ b, float* __restrict__ out) {
    __shared__ float Ws[D * C];
    int tid = threadIdx.x;
    for (int p = tid; p < D * C; p += 256) Ws[p] = W[p];
    __syncthreads();
    int i = blockIdx.x * 16 + (tid >> 4);
    int c = tid & 15;
    const float* xr = X + i * D;
    float acc = b[c];
#pragma unroll 8
    for (int d = 0; d < D; d++) acc = fmaf(xr[d], Ws[d * C + c], acc);
    g_Y[i * C + c] = acc;
    out[i * C + c] = acc;
}

// ---------------------------------------------------------------------------
// KNN candidate GEMM: CTA 128(i) x 128(j), 256 threads = 8 warps (2m x 4n),
// warp tile 64x32. K stages of 64 bf16 cols, 12 stages/jt, 3-stage cp.async
// ring, ONE __syncthreads per stage. XOR-swizzled smem (128B rows):
//   offset(row, c16) = row*128 + ((c16 ^ (row&7)) * 16)
// -> conflict-free cp.async stores AND ldmatrix reads, no padding.
// Stage buffers: buf s%3 at s*32768 (A 16KB then B 16KB).
// ---------------------------------------------------------------------------
#define STAGEB  32768
#define SQ_OFF  98304
#define CD_OFF  98816
#define KNN_SMEM (CD_OFF + 128 * 4 * 16)      // 107008

__device__ __forceinline__ void issue_stage(u32 smb, int stage, int irow0,
                                            int jbase, int tid) {
    u32 buf = smb + (u32)(stage % 3) * STAGEB;
    const __nv_bfloat16* eA = g_E + irow0 * 384 + g_aoff64[stage];
    const __nv_bfloat16* eB = g_E + jbase * 384 + g_boff64[stage];
#pragma unroll
    for (int p = 0; p < 4; p++) {
        int s   = tid + p * 256;
        int row = s >> 3, c16 = s & 7;
        u32 off = (u32)(row * 128 + ((c16 ^ (row & 7)) * 16));
        cp16(buf + off,         eA + row * 384 + c16 * 8);
        cp16(buf + 16384 + off, eB + row * 384 + c16 * 8);
    }
}

__global__ __launch_bounds__(256, 2) void knn_mma_kernel() {
    extern __shared__ char smraw[];
    const u32 smb = smem_u32(smraw);
    float* sSq  = (float*)(smraw + SQ_OFF);
    u64*   scnd = (u64*)(smraw + CD_OFF);      // [128 rows][4 warp_n][2]

    const int tid  = threadIdx.x;
    const int wid  = tid >> 5;
    const int lane = tid & 31;
    const int g    = lane >> 2;
    const int cq   = lane & 3;
    const int warp_m = wid >> 2;               // 0..1
    const int warp_n = wid & 3;                // 0..3
    const int itile  = blockIdx.x >> 3;
    const int jq     = blockIdx.x & 7;
    const int irow0  = itile * 128;

    for (int p = tid; p < 128 * 4 * 2; p += 256) scnd[p] = ~0ull;

    // per-lane ldmatrix invariants (XOR swizzle; row&7 == lane&7 everywhere)
    const u32 aRow = (u32)((warp_m * 64 + (lane & 15)) * 128);
    const u32 aX   = (u32)(lane >> 4);          // 0/1 -> k-half
    const u32 bRow = (u32)(16384 + (warp_n * 32 + (lane & 7)) * 128);
    const u32 bX   = (u32)((lane >> 3) & 1);
    const u32 sw   = (u32)(lane & 7);

    for (int jt = 0; jt < 8; jt++) {
        const int jbase = (jq * 8 + jt) * 128;
        __syncthreads();                       // prev jt fully done (bufs+sSq)
        issue_stage(smb, 0, irow0, jbase, tid); CP_COMMIT();
        issue_stage(smb, 1, irow0, jbase, tid); CP_COMMIT();
        if (tid < 128) sSq[tid] = g_sq[jbase + tid];

        float acc[4][4][4];
#pragma unroll
        for (int mt = 0; mt < 4; mt++)
#pragma unroll
            for (int nt = 0; nt < 4; nt++)
#pragma unroll
                for (int q = 0; q < 4; q++) acc[mt][nt][q] = 0.f;

#pragma unroll 1
        for (int kc = 0; kc < 12; kc++) {
            CP_WAIT1();                        // stage kc landed (in-order groups)
            __syncthreads();                   // visible everywhere; prev reads done
            if (kc < 10) issue_stage(smb, kc + 2, irow0, jbase, tid);
            CP_COMMIT();                       // empty commits keep count uniform
            u32 buf = smb + (u32)(kc % 3) * STAGEB;
#pragma unroll
            for (int k16 = 0; k16 < 4; k16++) {
                u32 af[4][4], bf[4][2];
#pragma unroll
                for (int mt = 0; mt < 4; mt++)
                    ldmx4(af[mt][0], af[mt][1], af[mt][2], af[mt][3],
                          buf + aRow + (u32)(mt * 2048)
                              + (((2u * k16 + aX) ^ sw) * 16));
#pragma unroll
                for (int nt = 0; nt < 4; nt++)
                    ldmx2(bf[nt][0], bf[nt][1],
                          buf + bRow + (u32)(nt * 1024)
                              + (((2u * k16 + bX) ^ sw) * 16));
#pragma unroll
                for (int mt = 0; mt < 4; mt++)
#pragma unroll
                    for (int nt = 0; nt < 4; nt++)
                        mma_bf16(acc[mt][nt], af[mt], bf[nt]);
            }
        }

        // ---- fused top-2 epilogue (recall): v = sq_j - 2*dot ----
#pragma unroll
        for (int mt = 0; mt < 4; mt++)
#pragma unroll
            for (int h = 0; h < 2; h++) {
                int rloc = warp_m * 64 + mt * 16 + g + h * 8;
                int irow = irow0 + rloc;
                u64 t0 = ~0ull, t1 = ~0ull;
#pragma unroll
                for (int nt = 0; nt < 4; nt++)
#pragma unroll
                    for (int q = 0; q < 2; q++) {
                        int cloc = warp_n * 32 + nt * 8 + 2 * cq + q;
                        int j = jbase + cloc;
                        float v = fmaf(-2.f, acc[mt][nt][h * 2 + q], sSq[cloc]);
                        if (j != irow) {
                            u64 key = pack_key(v, j);
                            if (key < t0) { t1 = t0; t0 = key; }
                            else if (key < t1) t1 = key;
                        }
                    }
#pragma unroll
                for (int o = 1; o <= 2; o <<= 1) {
                    u64 o0 = __shfl_xor_sync(0xffffffffu, t0, o);
                    u64 o1 = __shfl_xor_sync(0xffffffffu, t1, o);
                    merge2(t0, t1, o0, o1);
                }
                if (cq == 0) {
                    u64* slot = &scnd[(rloc * 4 + warp_n) * 2];
                    u64 s0 = slot[0], s1 = slot[1];
                    merge2(s0, s1, t0, t1);
                    slot[0] = s0; slot[1] = s1;
                }
            }
    }

    __syncthreads();
    if (tid < 128) {
        u64 b0 = ~0ull, b1 = ~0ull;
#pragma unroll
        for (int q = 0; q < 8; q++) {
            u64 k = scnd[tid * 8 + q];
            if (k < b0) { b1 = b0; b0 = k; }
            else if (k < b1) b1 = k;
        }
        int ig = irow0 + tid;
        g_cand[(ig * 8 + jq) * 2 + 0] = b0;
        g_cand[(ig * 8 + jq) * 2 + 1] = b1;
    }
}

// ---------------------------------------------------------------------------
// Refinement with EXACTLY the R2 comparator (unchanged)
// ---------------------------------------------------------------------------
__global__ void refine_kernel(const float* __restrict__ X) {
    int tid = threadIdx.x;
    int row = blockIdx.x * 16 + (tid >> 4);
    int c   = tid & 15;
    u32 j   = (u32)g_cand[row * 16 + c];
    u64 k2  = ~0ull;
    if (j < T) {
        const float* xi = X + row * D;
        const float* xj = X + j * D;
        float acc = 0.f;
#pragma unroll 16
        for (int k = 0; k < D; k++) acc = fmaf(xi[k], xj[k], acc);
        float v = g_sq[j] - 2.0f * acc;
        k2 = pack_key(v, (int)j);
    }
    u64 t0 = k2, t1 = ~0ull;
#pragma unroll
    for (int o = 1; o < 16; o <<= 1) {
        u64 o0 = __shfl_xor_sync(0xffffffffu, t0, o);
        u64 o1 = __shfl_xor_sync(0xffffffffu, t1, o);
        merge2(t0, t1, o0, o1);
    }
    if (c == 0) {
        g_nbr[row * 2 + 0] = (int)(u32)t0;
        g_nbr[row * 2 + 1] = (int)(u32)t1;
    }
}

// ---------------------------------------------------------------------------
__global__ void syn_kernel(const int* __restrict__ nn_idx,
                           const float* __restrict__ gaps,
                           float* __restrict__ out) {
    int idx = blockIdx.x * 256 + threadIdx.x;
    int s   = idx >> 4;
    int c   = idx & 15;
    int src = s >> 2;
    int k   = nn_idx[s] & 1;
    int ch  = g_nbr[src * 2 + k];
    float g  = gaps[s];
    float ys = g_Y[src * C + c];
    float yc = g_Y[ch * C + c];
    out[(T + s) * C + c] = ys + g * (yc - ys);
}

// ---------------------------------------------------------------------------
extern "C" void kernel_launch(void* const* d_in, const int* in_sizes, int n_in,
                              void* d_out, int out_size) {
    const float* X      = (const float*)d_in[0];
    const int*   nn_idx = (const int*)d_in[1];
    const float* gaps   = (const float*)d_in[2];
    const float* W      = (const float*)d_in[3];
    const float* b      = (const float*)d_in[4];
    float* out = (float*)d_out;

    cudaFuncSetAttribute(knn_mma_kernel,
                         cudaFuncAttributeMaxDynamicSharedMemorySize, KNN_SMEM);

    split_kernel  <<<T * D / 4 / 256, 256>>>(X);
    sq_kernel     <<<T / 8,  256>>>(X);
    y_kernel      <<<T / 16, 256>>>(X, W, b, out);
    knn_mma_kernel<<<64 * 8, 256, KNN_SMEM>>>();
    refine_kernel <<<T / 16, 256>>>(X);
    syn_kernel    <<<NM * T * C / 256, 256>>>(nn_idx, gaps, out);
}

// round 16
// speedup vs baseline: 3.1243x; 1.2745x over previous
#include <cuda_runtime.h>
#include <cuda_bf16.h>
#include <cstdint>

#define T 8192
#define D 128
#define C 16
#define NM 4

typedef unsigned long long u64;
typedef unsigned int u32;

// ---- device scratch (no allocations allowed) ----
__device__ float g_sq[T];
__device__ float g_Y[T * C];
__device__ int   g_nbr[T * 2];
__device__ __nv_bfloat16 g_E[T * 256];   // [h | m] bf16 split, 4MB
__device__ u64   g_cand[T * 8 * 2];      // per-row, per-j-octant top-2 keys

// 64-col stage offsets into E's 256 cols. Products: hh, hm, mh, mm
// (A 128-pairs: h,m,h,m ; B: h,h,m,m). l-terms dropped: MMA is recall-only,
// the refine_kernel re-ranks with the exact fp32 comparator.
__device__ const int g_aoff64[8] = {0,64, 128,192, 0,64, 128,192};
__device__ const int g_boff64[8] = {0,64, 0,64, 128,192, 128,192};

__device__ __forceinline__ u64 pack_key(float v, int j) {
    u32 f = __float_as_uint(v);
    f ^= (u32)((int)f >> 31) | 0x80000000u;
    return ((u64)f << 32) | (u32)j;
}

__device__ __forceinline__ void merge2(u64& s0, u64& s1, u64 t0, u64 t1) {
    u64 lo = t0 < s0 ? t0 : s0;
    u64 hi = t0 < s0 ? s0 : t0;
    u64 m1 = t1 < s1 ? t1 : s1;
    s1 = hi < m1 ? hi : m1;
    s0 = lo;
}

__device__ __forceinline__ u32 smem_u32(const void* p) {
    u32 a;
    asm("{ .reg .u64 t; cvta.to.shared.u64 t, %1; cvt.u32.u64 %0, t; }"
        : "=r"(a) : "l"(p));
    return a;
}

__device__ __forceinline__ void mma_bf16(float* d, const u32* a, const u32* b) {
    asm volatile(
        "mma.sync.aligned.m16n8k16.row.col.f32.bf16.bf16.f32 "
        "{%0,%1,%2,%3}, {%4,%5,%6,%7}, {%8,%9}, {%0,%1,%2,%3};"
        : "+f"(d[0]), "+f"(d[1]), "+f"(d[2]), "+f"(d[3])
        : "r"(a[0]), "r"(a[1]), "r"(a[2]), "r"(a[3]), "r"(b[0]), "r"(b[1]));
}

__device__ __forceinline__ void ldmx4(u32& r0, u32& r1, u32& r2, u32& r3, u32 a) {
    asm volatile("ldmatrix.sync.aligned.m8n8.x4.shared.b16 {%0,%1,%2,%3}, [%4];"
                 : "=r"(r0), "=r"(r1), "=r"(r2), "=r"(r3) : "r"(a));
}
__device__ __forceinline__ void ldmx2(u32& r0, u32& r1, u32 a) {
    asm volatile("ldmatrix.sync.aligned.m8n8.x2.shared.b16 {%0,%1}, [%2];"
                 : "=r"(r0), "=r"(r1) : "r"(a));
}

__device__ __forceinline__ void cp16(u32 dst, const __nv_bfloat16* src) {
    asm volatile("cp.async.cg.shared.global [%0], [%1], 16;"
                 :: "r"(dst), "l"(src) : "memory");
}
#define CP_COMMIT() asm volatile("cp.async.commit_group;" ::: "memory")
#define CP_WAIT1()  asm volatile("cp.async.wait_group 1;"  ::: "memory")

// ---------------------------------------------------------------------------
// 2-way bf16 split: x = h + m (+ dropped l); E[i] = [h(128) | m(128)]
// ---------------------------------------------------------------------------
__global__ void split_kernel(const float* __restrict__ X) {
    int i   = blockIdx.x * 256 + threadIdx.x;
    int row = i >> 5;
    int kq  = (i & 31) * 4;
    float4 v = ((const float4*)X)[i];
    float xs[4] = {v.x, v.y, v.z, v.w};
    __nv_bfloat16 h[4], m[4];
#pragma unroll
    for (int q = 0; q < 4; q++) {
        float x = xs[q];
        h[q] = __float2bfloat16(x);
        float r1 = x - __bfloat162float(h[q]);
        m[q] = __float2bfloat16(r1);
    }
    *(uint2*)&g_E[row * 256 + kq]       = *(uint2*)h;
    *(uint2*)&g_E[row * 256 + 128 + kq] = *(uint2*)m;
}

// ---------------------------------------------------------------------------
__global__ void sq_kernel(const float* __restrict__ X) {
    int row  = blockIdx.x * 8 + (threadIdx.x >> 5);
    int lane = threadIdx.x & 31;
    const float* xr = X + row * D;
    float s = 0.f;
#pragma unroll
    for (int q = 0; q < 4; q++) {
        float v = xr[lane + 32 * q];
        s = fmaf(v, v, s);
    }
#pragma unroll
    for (int o = 16; o; o >>= 1) s += __shfl_xor_sync(0xffffffffu, s, o);
    if (lane == 0) g_sq[row] = s;
}

// ---------------------------------------------------------------------------
__global__ void y_kernel(const float* __restrict__ X, const float* __restrict__ W,
                         const float* __restrict__ b, float* __restrict__ out) {
    __shared__ float Ws[D * C];
    int tid = threadIdx.x;
    for (int p = tid; p < D * C; p += 256) Ws[p] = W[p];
    __syncthreads();
    int i = blockIdx.x * 16 + (tid >> 4);
    int c = tid & 15;
    const float* xr = X + i * D;
    float acc = b[c];
#pragma unroll 8
    for (int d = 0; d < D; d++) acc = fmaf(xr[d], Ws[d * C + c], acc);
    g_Y[i * C + c] = acc;
    out[i * C + c] = acc;
}

// ---------------------------------------------------------------------------
// KNN candidate GEMM: CTA 128(i) x 128(j), 256 threads = 8 warps (2m x 4n),
// warp tile 64x32. K stages of 64 bf16 cols, 8 stages/jt, 3-stage cp.async
// ring, ONE __syncthreads per stage. XOR-swizzled smem (128B rows).
// ---------------------------------------------------------------------------
#define STAGEB  32768
#define SQ_OFF  98304
#define CD_OFF  98816
#define KNN_SMEM (CD_OFF + 128 * 4 * 16)      // 107008

__device__ __forceinline__ void issue_stage(u32 smb, int stage, int irow0,
                                            int jbase, int tid) {
    u32 buf = smb + (u32)(stage % 3) * STAGEB;
    const __nv_bfloat16* eA = g_E + irow0 * 256 + g_aoff64[stage];
    const __nv_bfloat16* eB = g_E + jbase * 256 + g_boff64[stage];
#pragma unroll
    for (int p = 0; p < 4; p++) {
        int s   = tid + p * 256;
        int row = s >> 3, c16 = s & 7;
        u32 off = (u32)(row * 128 + ((c16 ^ (row & 7)) * 16));
        cp16(buf + off,         eA + row * 256 + c16 * 8);
        cp16(buf + 16384 + off, eB + row * 256 + c16 * 8);
    }
}

__global__ __launch_bounds__(256, 2) void knn_mma_kernel() {
    extern __shared__ char smraw[];
    const u32 smb = smem_u32(smraw);
    float* sSq  = (float*)(smraw + SQ_OFF);
    u64*   scnd = (u64*)(smraw + CD_OFF);      // [128 rows][4 warp_n][2]

    const int tid  = threadIdx.x;
    const int wid  = tid >> 5;
    const int lane = tid & 31;
    const int g    = lane >> 2;
    const int cq   = lane & 3;
    const int warp_m = wid >> 2;               // 0..1
    const int warp_n = wid & 3;                // 0..3
    const int itile  = blockIdx.x >> 3;
    const int jq     = blockIdx.x & 7;
    const int irow0  = itile * 128;

    for (int p = tid; p < 128 * 4 * 2; p += 256) scnd[p] = ~0ull;

    // per-lane ldmatrix invariants (XOR swizzle; swizzle key = row&7)
    const u32 aRow = (u32)((warp_m * 64 + (lane & 15)) * 128);
    const u32 aX   = (u32)(lane >> 4);
    const u32 bRow = (u32)(16384 + (warp_n * 32 + (lane & 7)) * 128);
    const u32 bX   = (u32)((lane >> 3) & 1);
    const u32 sw   = (u32)(lane & 7);

    for (int jt = 0; jt < 8; jt++) {
        const int jbase = (jq * 8 + jt) * 128;
        __syncthreads();                       // prev jt fully done (bufs+sSq)
        issue_stage(smb, 0, irow0, jbase, tid); CP_COMMIT();
        issue_stage(smb, 1, irow0, jbase, tid); CP_COMMIT();
        if (tid < 128) sSq[tid] = g_sq[jbase + tid];

        float acc[4][4][4];
#pragma unroll
        for (int mt = 0; mt < 4; mt++)
#pragma unroll
            for (int nt = 0; nt < 4; nt++)
#pragma unroll
                for (int q = 0; q < 4; q++) acc[mt][nt][q] = 0.f;

#pragma unroll 1
        for (int kc = 0; kc < 8; kc++) {
            CP_WAIT1();                        // stage kc landed (in-order groups)
            __syncthreads();                   // visible; prev stage reads done
            if (kc < 6) issue_stage(smb, kc + 2, irow0, jbase, tid);
            CP_COMMIT();                       // empty commits keep count uniform
            u32 buf = smb + (u32)(kc % 3) * STAGEB;
#pragma unroll
            for (int k16 = 0; k16 < 4; k16++) {
                u32 af[4][4], bf[4][2];
#pragma unroll
                for (int mt = 0; mt < 4; mt++)
                    ldmx4(af[mt][0], af[mt][1], af[mt][2], af[mt][3],
                          buf + aRow + (u32)(mt * 2048)
                              + (((2u * k16 + aX) ^ sw) * 16));
#pragma unroll
                for (int nt = 0; nt < 4; nt++)
                    ldmx2(bf[nt][0], bf[nt][1],
                          buf + bRow + (u32)(nt * 1024)
                              + (((2u * k16 + bX) ^ sw) * 16));
#pragma unroll
                for (int mt = 0; mt < 4; mt++)
#pragma unroll
                    for (int nt = 0; nt < 4; nt++)
                        mma_bf16(acc[mt][nt], af[mt], bf[nt]);
            }
        }

        // ---- fused top-2 epilogue (recall): v = sq_j - 2*dot ----
#pragma unroll
        for (int mt = 0; mt < 4; mt++)
#pragma unroll
            for (int h = 0; h < 2; h++) {
                int rloc = warp_m * 64 + mt * 16 + g + h * 8;
                int irow = irow0 + rloc;
                u64 t0 = ~0ull, t1 = ~0ull;
#pragma unroll
                for (int nt = 0; nt < 4; nt++)
#pragma unroll
                    for (int q = 0; q < 2; q++) {
                        int cloc = warp_n * 32 + nt * 8 + 2 * cq + q;
                        int j = jbase + cloc;
                        float v = fmaf(-2.f, acc[mt][nt][h * 2 + q], sSq[cloc]);
                        if (j != irow) {
                            u64 key = pack_key(v, j);
                            if (key < t0) { t1 = t0; t0 = key; }
                            else if (key < t1) t1 = key;
                        }
                    }
#pragma unroll
                for (int o = 1; o <= 2; o <<= 1) {
                    u64 o0 = __shfl_xor_sync(0xffffffffu, t0, o);
                    u64 o1 = __shfl_xor_sync(0xffffffffu, t1, o);
                    merge2(t0, t1, o0, o1);
                }
                if (cq == 0) {
                    u64* slot = &scnd[(rloc * 4 + warp_n) * 2];
                    u64 s0 = slot[0], s1 = slot[1];
                    merge2(s0, s1, t0, t1);
                    slot[0] = s0; slot[1] = s1;
                }
            }
    }

    __syncthreads();
    if (tid < 128) {
        u64 b0 = ~0ull, b1 = ~0ull;
#pragma unroll
        for (int q = 0; q < 8; q++) {
            u64 k = scnd[tid * 8 + q];
            if (k < b0) { b1 = b0; b0 = k; }
            else if (k < b1) b1 = k;
        }
        int ig = irow0 + tid;
        g_cand[(ig * 8 + jq) * 2 + 0] = b0;
        g_cand[(ig * 8 + jq) * 2 + 1] = b1;
    }
}

// ---------------------------------------------------------------------------
// Refinement with EXACTLY the R2 comparator (unchanged)
// ---------------------------------------------------------------------------
__global__ void refine_kernel(const float* __restrict__ X) {
    int tid = threadIdx.x;
    int row = blockIdx.x * 16 + (tid >> 4);
    int c   = tid & 15;
    u32 j   = (u32)g_cand[row * 16 + c];
    u64 k2  = ~0ull;
    if (j < T) {
        const float* xi = X + row * D;
        const float* xj = X + j * D;
        float acc = 0.f;
#pragma unroll 16
        for (int k = 0; k < D; k++) acc = fmaf(xi[k], xj[k], acc);
        float v = g_sq[j] - 2.0f * acc;
        k2 = pack_key(v, (int)j);
    }
    u64 t0 = k2, t1 = ~0ull;
#pragma unroll
    for (int o = 1; o < 16; o <<= 1) {
        u64 o0 = __shfl_xor_sync(0xffffffffu, t0, o);
        u64 o1 = __shfl_xor_sync(0xffffffffu, t1, o);
        merge2(t0, t1, o0, o1);
    }
    if (c == 0) {
        g_nbr[row * 2 + 0] = (int)(u32)t0;
        g_nbr[row * 2 + 1] = (int)(u32)t1;
    }
}

// ---------------------------------------------------------------------------
__global__ void syn_kernel(const int* __restrict__ nn_idx,
                           const float* __restrict__ gaps,
                           float* __restrict__ out) {
    int idx = blockIdx.x * 256 + threadIdx.x;
    int s   = idx >> 4;
    int c   = idx & 15;
    int src = s >> 2;
    int k   = nn_idx[s] & 1;
    int ch  = g_nbr[src * 2 + k];
    float g  = gaps[s];
    float ys = g_Y[src * C + c];
    float yc = g_Y[ch * C + c];
    out[(T + s) * C + c] = ys + g * (yc - ys);
}

// ---------------------------------------------------------------------------
extern "C" void kernel_launch(void* const* d_in, const int* in_sizes, int n_in,
                              void* d_out, int out_size) {
    const float* X      = (const float*)d_in[0];
    const int*   nn_idx = (const int*)d_in[1];
    const float* gaps   = (const float*)d_in[2];
    const float* W      = (const float*)d_in[3];
    const float* b      = (const float*)d_in[4];
    float* out = (float*)d_out;

    cudaFuncSetAttribute(knn_mma_kernel,
                         cudaFuncAttributeMaxDynamicSharedMemorySize, KNN_SMEM);

    split_kernel  <<<T * D / 4 / 256, 256>>>(X);
    sq_kernel     <<<T / 8,  256>>>(X);
    y_kernel      <<<T / 16, 256>>>(X, W, b, out);
    knn_mma_kernel<<<64 * 8, 256, KNN_SMEM>>>();
    refine_kernel <<<T / 16, 256>>>(X);
    syn_kernel    <<<NM * T * C / 256, 256>>>(nn_idx, gaps, out);
}

// round 17
// speedup vs baseline: 4.3468x; 1.3913x over previous
#include <cuda_runtime.h>
#include <cuda_bf16.h>
#include <cstdint>

#define T 8192
#define D 128
#define C 16
#define NM 4

typedef unsigned long long u64;
typedef unsigned int u32;

// ---- device scratch (no allocations allowed) ----
__device__ float g_sq[T];
__device__ float g_Y[T * C];
__device__ int   g_nbr[T * 2];
__device__ __nv_bfloat16 g_E[T * 256];   // [h | m] bf16 split, 4MB
__device__ u64   g_cand2[T * 64 * 2];    // per-row, per-partner-tile top-2 (8MB)
__device__ u64   g_cand[T * 16];         // per-row, 8 groups x top-2 (refine input)

// 64-col stage offsets into E's 256 cols. Products: hh, hm, mh, mm
// (A 128-pairs: h,m,h,m ; B: h,h,m,m) — symmetric product set, so the tile
// value is orientation-independent. MMA is recall-only; refine re-ranks exact.
__device__ const int g_aoff64[8] = {0,64, 128,192, 0,64, 128,192};
__device__ const int g_boff64[8] = {0,64, 0,64, 128,192, 128,192};

__device__ __forceinline__ u64 pack_key(float v, int j) {
    u32 f = __float_as_uint(v);
    f ^= (u32)((int)f >> 31) | 0x80000000u;
    return ((u64)f << 32) | (u32)j;
}

__device__ __forceinline__ void merge2(u64& s0, u64& s1, u64 t0, u64 t1) {
    u64 lo = t0 < s0 ? t0 : s0;
    u64 hi = t0 < s0 ? s0 : t0;
    u64 m1 = t1 < s1 ? t1 : s1;
    s1 = hi < m1 ? hi : m1;
    s0 = lo;
}

__device__ __forceinline__ void ins2(u64& t0, u64& t1, u64 k) {
    if (k < t0) { t1 = t0; t0 = k; }
    else if (k < t1) t1 = k;
}

__device__ __forceinline__ u32 smem_u32(const void* p) {
    u32 a;
    asm("{ .reg .u64 t; cvta.to.shared.u64 t, %1; cvt.u32.u64 %0, t; }"
        : "=r"(a) : "l"(p));
    return a;
}

__device__ __forceinline__ void mma_bf16(float* d, const u32* a, const u32* b) {
    asm volatile(
        "mma.sync.aligned.m16n8k16.row.col.f32.bf16.bf16.f32 "
        "{%0,%1,%2,%3}, {%4,%5,%6,%7}, {%8,%9}, {%0,%1,%2,%3};"
        : "+f"(d[0]), "+f"(d[1]), "+f"(d[2]), "+f"(d[3])
        : "r"(a[0]), "r"(a[1]), "r"(a[2]), "r"(a[3]), "r"(b[0]), "r"(b[1]));
}

__device__ __forceinline__ void ldmx4(u32& r0, u32& r1, u32& r2, u32& r3, u32 a) {
    asm volatile("ldmatrix.sync.aligned.m8n8.x4.shared.b16 {%0,%1,%2,%3}, [%4];"
                 : "=r"(r0), "=r"(r1), "=r"(r2), "=r"(r3) : "r"(a));
}
__device__ __forceinline__ void ldmx2(u32& r0, u32& r1, u32 a) {
    asm volatile("ldmatrix.sync.aligned.m8n8.x2.shared.b16 {%0,%1}, [%2];"
                 : "=r"(r0), "=r"(r1) : "r"(a));
}

__device__ __forceinline__ void cp16(u32 dst, const __nv_bfloat16* src) {
    asm volatile("cp.async.cg.shared.global [%0], [%1], 16;"
                 :: "r"(dst), "l"(src) : "memory");
}
#define CP_COMMIT() asm volatile("cp.async.commit_group;" ::: "memory")
#define CP_WAIT1()  asm volatile("cp.async.wait_group 1;"  ::: "memory")

// ---------------------------------------------------------------------------
__global__ void split_kernel(const float* __restrict__ X) {
    int i   = blockIdx.x * 256 + threadIdx.x;
    int row = i >> 5;
    int kq  = (i & 31) * 4;
    float4 v = ((const float4*)X)[i];
    float xs[4] = {v.x, v.y, v.z, v.w};
    __nv_bfloat16 h[4], m[4];
#pragma unroll
    for (int q = 0; q < 4; q++) {
        float x = xs[q];
        h[q] = __float2bfloat16(x);
        float r1 = x - __bfloat162float(h[q]);
        m[q] = __float2bfloat16(r1);
    }
    *(uint2*)&g_E[row * 256 + kq]       = *(uint2*)h;
    *(uint2*)&g_E[row * 256 + 128 + kq] = *(uint2*)m;
}

// ---------------------------------------------------------------------------
__global__ void sq_kernel(const float* __restrict__ X) {
    int row  = blockIdx.x * 8 + (threadIdx.x >> 5);
    int lane = threadIdx.x & 31;
    const float* xr = X + row * D;
    float s = 0.f;
#pragma unroll
    for (int q = 0; q < 4; q++) {
        float v = xr[lane + 32 * q];
        s = fmaf(v, v, s);
    }
#pragma unroll
    for (int o = 16; o; o >>= 1) s += __shfl_xor_sync(0xffffffffu, s, o);
    if (lane == 0) g_sq[row] = s;
}

// ---------------------------------------------------------------------------
__global__ void y_kernel(const float* __restrict__ X, const float* __restrict__ W,
                         const float* __restrict__ b, float* __restrict__ out) {
    __shared__ float Ws[D * C];
    int tid = threadIdx.x;
    for (int p = tid; p < D * C; p += 256) Ws[p] = W[p];
    __syncthreads();
    int i = blockIdx.x * 16 + (tid >> 4);
    int c = tid & 15;
    const float* xr = X + i * D;
    float acc = b[c];
#pragma unroll 8
    for (int d = 0; d < D; d++) acc = fmaf(xr[d], Ws[d * C + c], acc);
    g_Y[i * C + c] = acc;
    out[i * C + c] = acc;
}

// ---------------------------------------------------------------------------
// Symmetric-pair KNN candidate GEMM.
// Grid: 2080 CTAs, one unordered tile pair {a,b} (a<=b) each.
// CTA 128x128 tile, 256 threads = 8 warps (2m x 4n), warp tile 64x32,
// 8 K-stages of 64 bf16 cols, 3-stage cp.async ring, XOR-swizzled smem.
// Row-side epilogue: top-2 per row of a over cols of b -> g_cand2[row][b].
// Col-side epilogue (a!=b): top-2 per col (rows of b) over rows of a
//                        -> g_cand2[col][a].
// ---------------------------------------------------------------------------
#define STAGEB   32768
#define SQJ_OFF  98304
#define SQI_OFF  98816
#define CDR_OFF  99328                         // [128][4][2] u64 = 8KB
#define CDC_OFF  107520                        // [128][2][2] u64 = 4KB
#define KNN_SMEM 111616

__device__ __forceinline__ void issue_stage(u32 smb, int stage, int irow0,
                                            int jbase, int tid) {
    u32 buf = smb + (u32)(stage % 3) * STAGEB;
    const __nv_bfloat16* eA = g_E + irow0 * 256 + g_aoff64[stage];
    const __nv_bfloat16* eB = g_E + jbase * 256 + g_boff64[stage];
#pragma unroll
    for (int p = 0; p < 4; p++) {
        int s   = tid + p * 256;
        int row = s >> 3, c16 = s & 7;
        u32 off = (u32)(row * 128 + ((c16 ^ (row & 7)) * 16));
        cp16(buf + off,         eA + row * 256 + c16 * 8);
        cp16(buf + 16384 + off, eB + row * 256 + c16 * 8);
    }
}

__global__ __launch_bounds__(256, 2) void knn_mma_kernel() {
    extern __shared__ char smraw[];
    const u32 smb = smem_u32(smraw);
    float* sSqJ = (float*)(smraw + SQJ_OFF);
    float* sSqI = (float*)(smraw + SQI_OFF);
    u64*   cdr  = (u64*)(smraw + CDR_OFF);     // [128 rows][4 warp_n][2]
    u64*   cdc  = (u64*)(smraw + CDC_OFF);     // [128 cols][2 warp_m][2]

    const int tid  = threadIdx.x;
    const int wid  = tid >> 5;
    const int lane = tid & 31;
    const int g    = lane >> 2;
    const int cq   = lane & 3;
    const int warp_m = wid >> 2;               // 0..1
    const int warp_n = wid & 3;                // 0..3

    // decode unordered pair {a,b}, a<=b, from blockIdx
    int a = 0, rem = blockIdx.x;
#pragma unroll 1
    while (rem >= 64 - a) { rem -= 64 - a; a++; }
    const int b = a + rem;
    const int irow0 = a * 128;
    const int jbase = b * 128;

    issue_stage(smb, 0, irow0, jbase, tid); CP_COMMIT();
    issue_stage(smb, 1, irow0, jbase, tid); CP_COMMIT();
    if (tid < 128) sSqJ[tid] = g_sq[jbase + tid];
    else           sSqI[tid - 128] = g_sq[irow0 + tid - 128];

    // per-lane ldmatrix invariants (XOR swizzle; swizzle key = row&7)
    const u32 aRow = (u32)((warp_m * 64 + (lane & 15)) * 128);
    const u32 aX   = (u32)(lane >> 4);
    const u32 bRow = (u32)(16384 + (warp_n * 32 + (lane & 7)) * 128);
    const u32 bX   = (u32)((lane >> 3) & 1);
    const u32 sw   = (u32)(lane & 7);

    float acc[4][4][4];
#pragma unroll
    for (int mt = 0; mt < 4; mt++)
#pragma unroll
        for (int nt = 0; nt < 4; nt++)
#pragma unroll
            for (int q = 0; q < 4; q++) acc[mt][nt][q] = 0.f;

#pragma unroll 1
    for (int kc = 0; kc < 8; kc++) {
        CP_WAIT1();                            // stage kc landed (in-order groups)
        __syncthreads();                       // visible; prev stage reads done
        if (kc < 6) issue_stage(smb, kc + 2, irow0, jbase, tid);
        CP_COMMIT();                           // empty commits keep count uniform
        u32 buf = smb + (u32)(kc % 3) * STAGEB;
#pragma unroll
        for (int k16 = 0; k16 < 4; k16++) {
            u32 af[4][4], bf[4][2];
#pragma unroll
            for (int mt = 0; mt < 4; mt++)
                ldmx4(af[mt][0], af[mt][1], af[mt][2], af[mt][3],
                      buf + aRow + (u32)(mt * 2048)
                          + (((2u * k16 + aX) ^ sw) * 16));
#pragma unroll
            for (int nt = 0; nt < 4; nt++)
                ldmx2(bf[nt][0], bf[nt][1],
                      buf + bRow + (u32)(nt * 1024)
                          + (((2u * k16 + bX) ^ sw) * 16));
#pragma unroll
            for (int mt = 0; mt < 4; mt++)
#pragma unroll
                for (int nt = 0; nt < 4; nt++)
                    mma_bf16(acc[mt][nt], af[mt], bf[nt]);
        }
    }

    // ---- row-side epilogue: queries = rows of a, candidates = cols of b ----
#pragma unroll
    for (int mt = 0; mt < 4; mt++)
#pragma unroll
        for (int h = 0; h < 2; h++) {
            int rloc = warp_m * 64 + mt * 16 + g + h * 8;
            int irow = irow0 + rloc;
            u64 t0 = ~0ull, t1 = ~0ull;
#pragma unroll
            for (int nt = 0; nt < 4; nt++)
#pragma unroll
                for (int q = 0; q < 2; q++) {
                    int cloc = warp_n * 32 + nt * 8 + 2 * cq + q;
                    int j = jbase + cloc;
                    float v = fmaf(-2.f, acc[mt][nt][h * 2 + q], sSqJ[cloc]);
                    if (j != irow) ins2(t0, t1, pack_key(v, j));
                }
#pragma unroll
            for (int o = 1; o <= 2; o <<= 1) {
                u64 o0 = __shfl_xor_sync(0xffffffffu, t0, o);
                u64 o1 = __shfl_xor_sync(0xffffffffu, t1, o);
                merge2(t0, t1, o0, o1);
            }
            if (cq == 0) {
                cdr[(rloc * 4 + warp_n) * 2 + 0] = t0;
                cdr[(rloc * 4 + warp_n) * 2 + 1] = t1;
            }
        }

    // ---- col-side epilogue: queries = rows of b, candidates = rows of a ----
    if (a != b) {
        float sqiv[8];
#pragma unroll
        for (int mt = 0; mt < 4; mt++)
#pragma unroll
            for (int h = 0; h < 2; h++)
                sqiv[mt * 2 + h] = sSqI[warp_m * 64 + mt * 16 + g + h * 8];
#pragma unroll
        for (int nt = 0; nt < 4; nt++)
#pragma unroll
            for (int q = 0; q < 2; q++) {
                int cloc = warp_n * 32 + nt * 8 + 2 * cq + q;
                u64 t0 = ~0ull, t1 = ~0ull;
#pragma unroll
                for (int mt = 0; mt < 4; mt++)
#pragma unroll
                    for (int h = 0; h < 2; h++) {
                        int rloc = warp_m * 64 + mt * 16 + g + h * 8;
                        float v = fmaf(-2.f, acc[mt][nt][h * 2 + q],
                                       sqiv[mt * 2 + h]);
                        ins2(t0, t1, pack_key(v, irow0 + rloc));
                    }
                // merge across g-lanes (xor 4,8,16 leaves cq -> col fixed)
#pragma unroll
                for (int o = 4; o <= 16; o <<= 1) {
                    u64 o0 = __shfl_xor_sync(0xffffffffu, t0, o);
                    u64 o1 = __shfl_xor_sync(0xffffffffu, t1, o);
                    merge2(t0, t1, o0, o1);
                }
                if (g == 0) {
                    cdc[(cloc * 2 + warp_m) * 2 + 0] = t0;
                    cdc[(cloc * 2 + warp_m) * 2 + 1] = t1;
                }
            }
    }

    __syncthreads();
    if (tid < 128) {
        u64 b0 = ~0ull, b1 = ~0ull;
#pragma unroll
        for (int q = 0; q < 8; q++) {
            u64 k = cdr[tid * 8 + q];
            if (k < b0) { b1 = b0; b0 = k; }
            else if (k < b1) b1 = k;
        }
        g_cand2[((irow0 + tid) * 64 + b) * 2 + 0] = b0;
        g_cand2[((irow0 + tid) * 64 + b) * 2 + 1] = b1;
    } else if (a != b) {
        int c = tid - 128;
        u64 b0 = ~0ull, b1 = ~0ull;
#pragma unroll
        for (int q = 0; q < 4; q++) {
            u64 k = cdc[c * 4 + q];
            if (k < b0) { b1 = b0; b0 = k; }
            else if (k < b1) b1 = k;
        }
        g_cand2[((jbase + c) * 64 + a) * 2 + 0] = b0;
        g_cand2[((jbase + c) * 64 + a) * 2 + 1] = b1;
    }
}

// ---------------------------------------------------------------------------
// Gather: per row, 8 groups of 8 partner-tile slots (16 keys) -> top-2 each.
// Output format identical to the R13-R16 refine input.
// ---------------------------------------------------------------------------
__global__ void gather_kernel() {
    int idx = blockIdx.x * 256 + threadIdx.x;    // over T*8
    int row = idx >> 3;
    int grp = idx & 7;
    const u64* src = g_cand2 + (row * 64 + grp * 8) * 2;
    u64 b0 = ~0ull, b1 = ~0ull;
#pragma unroll
    for (int q = 0; q < 16; q++) {
        u64 k = src[q];
        if (k < b0) { b1 = b0; b0 = k; }
        else if (k < b1) b1 = k;
    }
    g_cand[row * 16 + grp * 2 + 0] = b0;
    g_cand[row * 16 + grp * 2 + 1] = b1;
}

// ---------------------------------------------------------------------------
// Refinement with EXACTLY the R2 comparator (unchanged)
// ---------------------------------------------------------------------------
__global__ void refine_kernel(const float* __restrict__ X) {
    int tid = threadIdx.x;
    int row = blockIdx.x * 16 + (tid >> 4);
    int c   = tid & 15;
    u32 j   = (u32)g_cand[row * 16 + c];
    u64 k2  = ~0ull;
    if (j < T) {
        const float* xi = X + row * D;
        const float* xj = X + j * D;
        float acc = 0.f;
#pragma unroll 16
        for (int k = 0; k < D; k++) acc = fmaf(xi[k], xj[k], acc);
        float v = g_sq[j] - 2.0f * acc;
        k2 = pack_key(v, (int)j);
    }
    u64 t0 = k2, t1 = ~0ull;
#pragma unroll
    for (int o = 1; o < 16; o <<= 1) {
        u64 o0 = __shfl_xor_sync(0xffffffffu, t0, o);
        u64 o1 = __shfl_xor_sync(0xffffffffu, t1, o);
        merge2(t0, t1, o0, o1);
    }
    if (c == 0) {
        g_nbr[row * 2 + 0] = (int)(u32)t0;
        g_nbr[row * 2 + 1] = (int)(u32)t1;
    }
}

// ---------------------------------------------------------------------------
__global__ void syn_kernel(const int* __restrict__ nn_idx,
                           const float* __restrict__ gaps,
                           float* __restrict__ out) {
    int idx = blockIdx.x * 256 + threadIdx.x;
    int s   = idx >> 4;
    int c   = idx & 15;
    int src = s >> 2;
    int k   = nn_idx[s] & 1;
    int ch  = g_nbr[src * 2 + k];
    float g  = gaps[s];
    float ys = g_Y[src * C + c];
    float yc = g_Y[ch * C + c];
    out[(T + s) * C + c] = ys + g * (yc - ys);
}

// ---------------------------------------------------------------------------
extern "C" void kernel_launch(void* const* d_in, const int* in_sizes, int n_in,
                              void* d_out, int out_size) {
    const float* X      = (const float*)d_in[0];
    const int*   nn_idx = (const int*)d_in[1];
    const float* gaps   = (const float*)d_in[2];
    const float* W      = (const float*)d_in[3];
    const float* b      = (const float*)d_in[4];
    float* out = (float*)d_out;

    cudaFuncSetAttribute(knn_mma_kernel,
                         cudaFuncAttributeMaxDynamicSharedMemorySize, KNN_SMEM);

    split_kernel  <<<T * D / 4 / 256, 256>>>(X);
    sq_kernel     <<<T / 8,  256>>>(X);
    y_kernel      <<<T / 16, 256>>>(X, W, b, out);
    knn_mma_kernel<<<2080, 256, KNN_SMEM>>>();
    gather_kernel <<<T * 8 / 256, 256>>>();
    refine_kernel <<<T / 16, 256>>>(X);
    syn_kernel    <<<NM * T * C / 256, 256>>>(nn_idx, gaps, out);
}